// round 7
// baseline (speedup 1.0000x reference)
#include <cuda_runtime.h>
#include <math.h>
#include <stdint.h>

// ---------------- scratch (device globals) ---------------------------------
__device__ float g_mixed[8192];
__device__ float g_z[4096];
__device__ float g_beta[32];
__device__ float g_a[32];
__device__ float g_outflat[4096];
__device__ int g_c1 = 0, g_c2 = 0, g_c3 = 0;

#define GRID 592
#define OFF_STATE 2048
#define OFF_CONV  (2048 + 524288)

// ---------------- ptx helpers ----------------------------------------------
__device__ __forceinline__ uint32_t smem_u32(const void* p) {
    uint32_t a;
    asm("{ .reg .u64 t; cvta.to.shared.u64 t, %1; cvt.u32.u64 %0, t; }"
        : "=r"(a) : "l"(p));
    return a;
}
__device__ __forceinline__ void mbar_init(uint32_t bar, uint32_t cnt) {
    asm volatile("mbarrier.init.shared.b64 [%0], %1;" :: "r"(bar), "r"(cnt) : "memory");
}
__device__ __forceinline__ void mbar_expect_tx(uint32_t bar, uint32_t bytes) {
    asm volatile("mbarrier.arrive.expect_tx.shared.b64 _, [%0], %1;"
                 :: "r"(bar), "r"(bytes) : "memory");
}
__device__ __forceinline__ void bulk_g2s(uint32_t dst, const void* src,
                                         uint32_t bytes, uint32_t bar) {
    asm volatile(
        "cp.async.bulk.shared::cluster.global.mbarrier::complete_tx::bytes "
        "[%0], [%1], %2, [%3];"
        :: "r"(dst), "l"(src), "r"(bytes), "r"(bar) : "memory");
}
__device__ __forceinline__ void mbar_wait(uint32_t bar, uint32_t parity) {
    asm volatile(
        "{\n\t.reg .pred P;\n"
        "W_%=:\n\t"
        "mbarrier.try_wait.parity.shared.b64 P, [%0], %1;\n\t"
        "@P bra D_%=;\n\t"
        "bra W_%=;\n"
        "D_%=:\n\t}"
        :: "r"(bar), "r"(parity) : "memory");
}

__device__ __forceinline__ float silu_f(float v) { return v / (1.f + expf(-v)); }
__device__ __forceinline__ float softplus_f(float v) {
    return (v > 20.f) ? v : log1pf(expf(v));
}
__device__ __forceinline__ float conv_silu(
    int c, const float* __restrict__ cs, const float* __restrict__ cw)
{
    float v = cs[c * 3 + 0] * cw[c * 4 + 0]
            + cs[c * 3 + 1] * cw[c * 4 + 1]
            + cs[c * 3 + 2] * cw[c * 4 + 2]
            + g_mixed[c]    * cw[c * 4 + 3];
    return silu_f(v);
}

// ---------------- the fused kernel ------------------------------------------
__global__ __launch_bounds__(256, 4) void k_fused(
    const float* __restrict__ x,
    const float* __restrict__ state,
    const float* __restrict__ conv_state,
    const float* __restrict__ W_qkv,
    const float* __restrict__ W_z,
    const float* __restrict__ W_b,
    const float* __restrict__ W_a,
    const float* __restrict__ conv_w,
    const float* __restrict__ A_log,
    const float* __restrict__ dt_bias,
    const float* __restrict__ norm_w,
    const float* __restrict__ W_out,
    float* __restrict__ out)
{
    __shared__ float sx[2048];     // 8 KB : x
    __shared__ float u[4096];      // 16 KB: K2 arrays (blocks<32) OR W_out slab
    __shared__ float red[8];
    __shared__ float sred[8];
    __shared__ __align__(8) unsigned long long mbar;

    int tid  = threadIdx.x;
    int warp = tid >> 5;
    int lane = tid & 31;
    int bid  = blockIdx.x;

    #pragma unroll
    for (int i = 0; i < 2; i++)
        ((float4*)sx)[tid + i * 256] = ((const float4*)x)[tid + i * 256];
    uint32_t mb = smem_u32(&mbar);
    if (tid == 0) mbar_init(mb, 1);
    __syncthreads();

    // ================= PHASE A : input GEMV (772 chunks of 16 rows) ========
    const float4* x4 = (const float4*)sx;
    for (int c = bid; c < 772; c += GRID) {
        int row0 = c * 16;
        const float* wbase;
        if (row0 < 8192)       wbase = W_qkv + (size_t)row0 * 2048;
        else if (row0 < 12288) wbase = W_z   + (size_t)(row0 - 8192) * 2048;
        else if (row0 < 12320) wbase = W_b   + (size_t)(row0 - 12288) * 2048;
        else                   wbase = W_a   + (size_t)(row0 - 12320) * 2048;

        int row = row0 + warp * 2;
        const float4* wa = (const float4*)wbase + (size_t)(warp * 2) * 512;
        const float4* wb = wa + 512;

        float acc0 = 0.f, acc1 = 0.f, acc2 = 0.f, acc3 = 0.f;
        #pragma unroll
        for (int i = 0; i < 4; i++) {
            float4 a[4], b[4];
            #pragma unroll
            for (int t = 0; t < 4; t++) {
                a[t] = __ldcs(&wa[(i * 4 + t) * 32 + lane]);
                b[t] = __ldcs(&wb[(i * 4 + t) * 32 + lane]);
            }
            #pragma unroll
            for (int t = 0; t < 4; t++) {
                float4 v = x4[(i * 4 + t) * 32 + lane];
                acc0 += a[t].x * v.x + a[t].y * v.y;
                acc1 += a[t].z * v.z + a[t].w * v.w;
                acc2 += b[t].x * v.x + b[t].y * v.y;
                acc3 += b[t].z * v.z + b[t].w * v.w;
            }
        }
        float accA = acc0 + acc1, accB = acc2 + acc3;
        #pragma unroll
        for (int o = 16; o; o >>= 1) {
            accA += __shfl_down_sync(0xffffffffu, accA, o);
            accB += __shfl_down_sync(0xffffffffu, accB, o);
        }
        if (lane == 0) {
            #pragma unroll
            for (int rr = 0; rr < 2; rr++) {
                int r = row + rr;
                float acc = rr ? accB : accA;
                if (r < 8192) {
                    g_mixed[r] = acc;
                    float* nc = out + OFF_CONV + (size_t)r * 3;
                    __stcs(&nc[0], conv_state[r * 3 + 1]);
                    __stcs(&nc[1], conv_state[r * 3 + 2]);
                    __stcs(&nc[2], acc);
                } else if (r < 12288) {
                    g_z[r - 8192] = acc;
                } else if (r < 12320) {
                    g_beta[r - 12288] = acc;
                } else {
                    g_a[r - 12320] = acc;
                }
            }
        }
    }
    __threadfence();
    __syncthreads();
    if (tid == 0) atomicAdd(&g_c1, 1);

    // prefetch first W_out row into smem (blocks that don't run K2)
    if (bid >= 32 && tid == 0) {
        mbar_expect_tx(mb, 16384);
        bulk_g2s(smem_u32(u), W_out + (size_t)bid * 4096, 16384, mb);
    }

    // ================= PHASE B : per-head delta rule (blocks 0..31) =========
    if (bid < 32) {
        if (tid == 0) {
            while (*(volatile int*)&g_c1 != GRID) __nanosleep(64);
        }
        __syncthreads();
        __threadfence();

        int h = bid;
        float* skv    = u;            // [8][128]
        float* ssqv   = u + 1024;     // [8][128]
        float* sq     = u + 2048;
        float* sk     = u + 2176;
        float* sv     = u + 2304;
        float* sdelta = u + 2432;

        if (tid < 128) {
            int grp = h >> 1;
            sq[tid] = conv_silu(grp * 128 + tid,        conv_state, conv_w);
            sk[tid] = conv_silu(2048 + grp * 128 + tid, conv_state, conv_w);
            sv[tid] = conv_silu(4096 + h * 128 + tid,   conv_state, conv_w);
        }
        __syncthreads();

        // block reductions (256 threads)
        float vq = tid < 128 ? sq[tid] * sq[tid] : 0.f;
        float vk = tid < 128 ? sk[tid] * sk[tid] : 0.f;
        #pragma unroll
        for (int o = 16; o; o >>= 1) {
            vq += __shfl_down_sync(0xffffffffu, vq, o);
            vk += __shfl_down_sync(0xffffffffu, vk, o);
        }
        if (lane == 0) { red[warp] = vq; sred[warp] = vk; }
        __syncthreads();
        float q2 = red[0] + red[1] + red[2] + red[3] + red[4] + red[5] + red[6] + red[7];
        float k2 = sred[0] + sred[1] + sred[2] + sred[3] + sred[4] + sred[5] + sred[6] + sred[7];
        __syncthreads();
        const float inv_sqrt128 = 0.08838834764831845f;
        if (tid < 128) {
            sq[tid] = sq[tid] * rsqrtf(q2 + 1e-6f) * inv_sqrt128;
            sk[tid] = sk[tid] * rsqrtf(k2 + 1e-6f);
        }
        __syncthreads();
        float vqk = tid < 128 ? sq[tid] * sk[tid] : 0.f;
        #pragma unroll
        for (int o = 16; o; o >>= 1) vqk += __shfl_down_sync(0xffffffffu, vqk, o);
        if (lane == 0) red[warp] = vqk;
        __syncthreads();
        float qk = red[0] + red[1] + red[2] + red[3] + red[4] + red[5] + red[6] + red[7];
        __syncthreads();

        float g    = expf(-expf(A_log[h]) * softplus_f(g_a[h] + dt_bias[h]));
        float beta = 1.f / (1.f + expf(-g_beta[h]));

        // pass 1: accumulate kv/sqv (raw, fold g later); 8 slices x 16 rows
        const float4* S4 = (const float4*)(state + (size_t)h * 16384);
        int cg = lane, sl = warp;
        float4 kv  = make_float4(0.f, 0.f, 0.f, 0.f);
        float4 sqv = make_float4(0.f, 0.f, 0.f, 0.f);
        #pragma unroll
        for (int r = 0; r < 16; r++) {
            int kk = sl * 16 + r;
            float4 s = S4[kk * 32 + cg];
            float kkv = sk[kk], qqv = sq[kk];
            kv.x  += s.x * kkv; kv.y  += s.y * kkv; kv.z  += s.z * kkv; kv.w  += s.w * kkv;
            sqv.x += s.x * qqv; sqv.y += s.y * qqv; sqv.z += s.z * qqv; sqv.w += s.w * qqv;
        }
        ((float4*)&skv[sl * 128])[cg]  = kv;
        ((float4*)&ssqv[sl * 128])[cg] = sqv;
        __syncthreads();

        float gated = 0.f;
        if (tid < 128) {
            float kvt = 0.f, sqvt = 0.f;
            #pragma unroll
            for (int s = 0; s < 8; s++) { kvt += skv[s * 128 + tid]; sqvt += ssqv[s * 128 + tid]; }
            kvt *= g; sqvt *= g;
            float delta = (sv[tid] - kvt) * beta;
            sdelta[tid] = delta;
            float o = sqvt + delta * qk;
            gated = o * silu_f(g_z[h * 128 + tid]);
        }
        __syncthreads();

        // pass 2: reload state (L2-hot) and write new_state
        float4 d4 = ((float4*)sdelta)[cg];
        float4* NS4 = (float4*)(out + OFF_STATE + (size_t)h * 16384);
        #pragma unroll
        for (int r = 0; r < 16; r++) {
            int kk = sl * 16 + r;
            float4 s = S4[kk * 32 + cg];
            float kkv = sk[kk];
            float4 w;
            w.x = s.x * g + kkv * d4.x;
            w.y = s.y * g + kkv * d4.y;
            w.z = s.z * g + kkv * d4.z;
            w.w = s.w * g + kkv * d4.w;
            __stcs(&NS4[kk * 32 + cg], w);
        }

        // rmsnorm + gate
        float gg = gated * gated;
        #pragma unroll
        for (int o = 16; o; o >>= 1) gg += __shfl_down_sync(0xffffffffu, gg, o);
        if (lane == 0) red[warp] = gg;
        __syncthreads();
        float m = (red[0] + red[1] + red[2] + red[3]) * (1.f / 128.f);
        if (tid < 128)
            g_outflat[h * 128 + tid] = gated * rsqrtf(m + 1e-6f) * norm_w[tid];
        __threadfence();
        __syncthreads();
        if (tid == 0) atomicAdd(&g_c2, 1);
    }

    // ================= PHASE C : output GEMV (2048 rows) ====================
    if (tid == 0) {
        while (*(volatile int*)&g_c2 != 32) __nanosleep(64);
    }
    __syncthreads();
    __threadfence();

    float4 xv[4];
    #pragma unroll
    for (int t = 0; t < 4; t++)
        xv[t] = ((const float4*)g_outflat)[t * 256 + tid];

    int rstart = bid;
    if (bid >= 32) {
        // first row from the prefetched smem slab
        if (tid == 0) mbar_wait(mb, 0);
        __syncthreads();
        const float4* w4 = (const float4*)u;
        float acc = 0.f;
        #pragma unroll
        for (int t = 0; t < 4; t++) {
            float4 a = w4[t * 256 + tid];
            acc += a.x * xv[t].x + a.y * xv[t].y + a.z * xv[t].z + a.w * xv[t].w;
        }
        #pragma unroll
        for (int o = 16; o; o >>= 1) acc += __shfl_down_sync(0xffffffffu, acc, o);
        if (lane == 0) sred[warp] = acc;
        __syncthreads();
        if (tid == 0) {
            float a = sred[0] + sred[1] + sred[2] + sred[3]
                    + sred[4] + sred[5] + sred[6] + sred[7];
            out[bid] = a;
        }
        __syncthreads();
        rstart = bid + GRID;
    }

    for (int r = rstart; r < 2048; r += GRID) {
        const float4* w4 = (const float4*)(W_out + (size_t)r * 4096);
        float acc = 0.f;
        #pragma unroll
        for (int t = 0; t < 4; t++) {
            float4 a = __ldcs(&w4[t * 256 + tid]);
            acc += a.x * xv[t].x + a.y * xv[t].y + a.z * xv[t].z + a.w * xv[t].w;
        }
        #pragma unroll
        for (int o = 16; o; o >>= 1) acc += __shfl_down_sync(0xffffffffu, acc, o);
        if (lane == 0) sred[warp] = acc;
        __syncthreads();
        if (tid == 0) {
            float a = sred[0] + sred[1] + sred[2] + sred[3]
                    + sred[4] + sred[5] + sred[6] + sred[7];
            out[r] = a;
        }
        __syncthreads();
    }

    // ---- counter reset for next graph replay ----
    if (tid == 0) {
        __threadfence();
        int old = atomicAdd(&g_c3, 1);
        if (old == GRID - 1) {
            g_c1 = 0;
            g_c2 = 0;
            __threadfence();
            g_c3 = 0;
        }
    }
}

// ---------------- launcher --------------------------------------------------
extern "C" void kernel_launch(void* const* d_in, const int* in_sizes, int n_in,
                              void* d_out, int out_size)
{
    const float* x          = (const float*)d_in[0];
    const float* state      = (const float*)d_in[1];
    const float* conv_state = (const float*)d_in[2];
    const float* W_qkv      = (const float*)d_in[3];
    const float* W_z        = (const float*)d_in[4];
    const float* W_b        = (const float*)d_in[5];
    const float* W_a        = (const float*)d_in[6];
    const float* conv_w     = (const float*)d_in[7];
    const float* A_log      = (const float*)d_in[8];
    const float* dt_bias    = (const float*)d_in[9];
    const float* norm_w     = (const float*)d_in[10];
    const float* W_out      = (const float*)d_in[11];
    float* out = (float*)d_out;

    k_fused<<<GRID, 256>>>(x, state, conv_state, W_qkv, W_z, W_b, W_a,
                           conv_w, A_log, dt_bias, norm_w, W_out, out);
}